// round 1
// baseline (speedup 1.0000x reference)
#include <cuda_runtime.h>
#include <stdint.h>

// RescaleProbMask: x (32, 256, 256, 16) fp32.
//   p[h,w]   = mean over (batch, channel)  -> 512 values per pixel
//   out      = p >= 0.25 ? x * 0.25/p : 1 - (0.75/(1-p)) * (1-x)
// Both branches are affine: out = scale * x + bias.
//
// Fused single-pass: one warp per (h,w) pixel. lane = batch index.
// Each lane loads its 16 channel values (4x float4, 64B contiguous),
// warp-shuffle reduces the sum, computes (scale, bias), applies FMA to the
// register-resident values, stores them back. x is read exactly once.

#define NB   32
#define NHW  (256 * 256)
#define NC   16
#define ALPHA 0.25f

__global__ __launch_bounds__(256, 8)
void rescale_prob_mask_kernel(const float* __restrict__ x,
                              float* __restrict__ out) {
    const int gwarp = (blockIdx.x * blockDim.x + threadIdx.x) >> 5;  // pixel id
    const int lane  = threadIdx.x & 31;                              // batch id

    // base element offset of x[lane, h, w, 0]
    const size_t base = (size_t)lane * ((size_t)NHW * NC) + (size_t)gwarp * NC;

    const float4* xp = reinterpret_cast<const float4*>(x + base);
    float4 v0 = xp[0];
    float4 v1 = xp[1];
    float4 v2 = xp[2];
    float4 v3 = xp[3];

    // per-lane partial sum of 16 channel values
    float s = (v0.x + v0.y) + (v0.z + v0.w)
            + (v1.x + v1.y) + (v1.z + v1.w)
            + (v2.x + v2.y) + (v2.z + v2.w)
            + (v3.x + v3.y) + (v3.z + v3.w);

    // warp-wide reduction over 32 batch lanes
    #pragma unroll
    for (int off = 16; off > 0; off >>= 1)
        s += __shfl_xor_sync(0xffffffffu, s, off);

    const float p = s * (1.0f / (NB * NC));

    float scale, bias;
    if (p >= ALPHA) {
        scale = ALPHA / p;
        bias  = 0.0f;
    } else {
        const float beta = (1.0f - ALPHA) / (1.0f - p);
        scale = beta;
        bias  = 1.0f - beta;
    }

    v0.x = fmaf(scale, v0.x, bias); v0.y = fmaf(scale, v0.y, bias);
    v0.z = fmaf(scale, v0.z, bias); v0.w = fmaf(scale, v0.w, bias);
    v1.x = fmaf(scale, v1.x, bias); v1.y = fmaf(scale, v1.y, bias);
    v1.z = fmaf(scale, v1.z, bias); v1.w = fmaf(scale, v1.w, bias);
    v2.x = fmaf(scale, v2.x, bias); v2.y = fmaf(scale, v2.y, bias);
    v2.z = fmaf(scale, v2.z, bias); v2.w = fmaf(scale, v2.w, bias);
    v3.x = fmaf(scale, v3.x, bias); v3.y = fmaf(scale, v3.y, bias);
    v3.z = fmaf(scale, v3.z, bias); v3.w = fmaf(scale, v3.w, bias);

    float4* op = reinterpret_cast<float4*>(out + base);
    op[0] = v0;
    op[1] = v1;
    op[2] = v2;
    op[3] = v3;
}

extern "C" void kernel_launch(void* const* d_in, const int* in_sizes, int n_in,
                              void* d_out, int out_size) {
    const float* x   = (const float*)d_in[0];
    float*       out = (float*)d_out;

    // one warp per pixel: 65536 warps, 8 warps (256 threads) per block
    const int threads = 256;
    const int blocks  = (NHW * 32) / threads;  // 8192
    rescale_prob_mask_kernel<<<blocks, threads>>>(x, out);
}

// round 2
// speedup vs baseline: 5.0064x; 5.0064x over previous
#include <cuda_runtime.h>
#include <stdint.h>

// RescaleProbMask: x (32, 256, 256, 16) fp32.
//   p[h,w] = mean over (batch, channel)            (512 values / pixel)
//   out    = p >= 0.25 ? x*0.25/p : 1 - (0.75/(1-p))*(1-x)
// Both branches affine: out = scale*x + bias.
//
// Coalesced fused single pass:
//   CTA (256 thr, 8 warps) handles 8 pixels.
//   Warp w covers batches 4w..4w+3; per batch it loads 512B contiguous
//   (32 lanes x float4) = the 8 pixels' 16 channels for that batch.
//   Lane L's 4 floats (per batch) all belong to pixel L/4, channels
//   [(L%4)*4, (L%4)*4+4). So:
//     lane sum (16 floats) -> shfl_xor(1),(2) over lane-groups-of-4
//     -> per-(warp,pixel) partial -> 8x8 smem reduce -> scale/bias
//     -> FMA register values -> coalesced stores.
// x is read exactly once; all LDG/STG.128 are 512B-contiguous per warp.

#define NB    32
#define NHW   (256 * 256)
#define NC    16
#define ALPHA 0.25f

#define PIX_PER_CTA 8
#define PLANE_F4    ((NHW * NC) / 4)   // float4s per batch plane = 262144

__global__ __launch_bounds__(256, 8)
void rescale_prob_mask_kernel(const float* __restrict__ x,
                              float* __restrict__ out) {
    __shared__ float psum[PIX_PER_CTA][8];   // [pixel][warp]

    const int tid  = threadIdx.x;
    const int warp = tid >> 5;
    const int lane = tid & 31;
    const int pix  = lane >> 2;              // pixel within CTA (0..7)

    // float4 index of this lane's slot within a batch plane
    const size_t slot = (size_t)blockIdx.x * (PIX_PER_CTA * NC / 4) + lane;

    const float4* __restrict__ xp = reinterpret_cast<const float4*>(x);
    float4*       __restrict__ op = reinterpret_cast<float4*>(out);

    // 4 batches per warp, front-batched loads for MLP
    const size_t i0 = (size_t)(warp * 4 + 0) * PLANE_F4 + slot;
    const size_t i1 = (size_t)(warp * 4 + 1) * PLANE_F4 + slot;
    const size_t i2 = (size_t)(warp * 4 + 2) * PLANE_F4 + slot;
    const size_t i3 = (size_t)(warp * 4 + 3) * PLANE_F4 + slot;
    float4 v0 = xp[i0];
    float4 v1 = xp[i1];
    float4 v2 = xp[i2];
    float4 v3 = xp[i3];

    // lane-local partial sum (4 batches x 4 channels of pixel `pix`)
    float s = ((v0.x + v0.y) + (v0.z + v0.w))
            + ((v1.x + v1.y) + (v1.z + v1.w))
            + ((v2.x + v2.y) + (v2.z + v2.w))
            + ((v3.x + v3.y) + (v3.z + v3.w));

    // reduce over the 4 lanes sharing a pixel (covers all 16 channels)
    s += __shfl_xor_sync(0xffffffffu, s, 1);
    s += __shfl_xor_sync(0xffffffffu, s, 2);

    // cross-warp reduce: one lane per pixel-group writes
    if ((lane & 3) == 0)
        psum[pix][warp] = s;
    __syncthreads();

    float tot = psum[pix][0] + psum[pix][1] + psum[pix][2] + psum[pix][3]
              + psum[pix][4] + psum[pix][5] + psum[pix][6] + psum[pix][7];

    const float p = tot * (1.0f / (NB * NC));

    float scale, bias;
    if (p >= ALPHA) {
        scale = ALPHA / p;
        bias  = 0.0f;
    } else {
        const float beta = (1.0f - ALPHA) / (1.0f - p);
        scale = beta;
        bias  = 1.0f - beta;
    }

    v0.x = fmaf(scale, v0.x, bias); v0.y = fmaf(scale, v0.y, bias);
    v0.z = fmaf(scale, v0.z, bias); v0.w = fmaf(scale, v0.w, bias);
    v1.x = fmaf(scale, v1.x, bias); v1.y = fmaf(scale, v1.y, bias);
    v1.z = fmaf(scale, v1.z, bias); v1.w = fmaf(scale, v1.w, bias);
    v2.x = fmaf(scale, v2.x, bias); v2.y = fmaf(scale, v2.y, bias);
    v2.z = fmaf(scale, v2.z, bias); v2.w = fmaf(scale, v2.w, bias);
    v3.x = fmaf(scale, v3.x, bias); v3.y = fmaf(scale, v3.y, bias);
    v3.z = fmaf(scale, v3.z, bias); v3.w = fmaf(scale, v3.w, bias);

    op[i0] = v0;
    op[i1] = v1;
    op[i2] = v2;
    op[i3] = v3;
}

extern "C" void kernel_launch(void* const* d_in, const int* in_sizes, int n_in,
                              void* d_out, int out_size) {
    const float* x   = (const float*)d_in[0];
    float*       out = (float*)d_out;

    const int blocks = NHW / PIX_PER_CTA;   // 8192
    rescale_prob_mask_kernel<<<blocks, 256>>>(x, out);
}